// round 7
// baseline (speedup 1.0000x reference)
#include <cuda_runtime.h>

// Problem constants
static constexpr int BATCH = 128;
static constexpr int W = 512;               // image is 512x512
static constexpr int NBLK = 4096;           // 64x64 blocks of 8x8 per image
static constexpr int L3N = 3 * NBLK;        // 12288 level-3 detail coeffs per batch
static constexpr int KMED_LO = (L3N / 2) - 1;  // 6143
static constexpr int KMED_HI = (L3N / 2);      // 6144
static constexpr int MED_THREADS = 256;
static constexpr int VPT = L3N / MED_THREADS;  // 48 values per thread

// Scratch (no cudaMalloc allowed): level-3 |details| + per-batch threshold
__device__ float g_l3abs[BATCH * L3N];
__device__ float g_thr[BATCH];

// ---------------------------------------------------------------------------
__global__ void k_zero(float* __restrict__ out) {
    if (threadIdx.x < 2) out[threadIdx.x] = 0.0f;
}

// ---------------------------------------------------------------------------
// Pass 1: per-thread 8x8 block -> level-3 abs details into scratch.
__global__ void k_pass1(const float* __restrict__ in) {
    const int batch = blockIdx.y;
    const int gb = blockIdx.x * blockDim.x + threadIdx.x;   // 0..4095
    const int br = gb >> 6;
    const int bc = gb & 63;
    const float* src = in + ((size_t)batch << 18) + (size_t)(br << 3) * W + (bc << 3);

    float cA1[4][4];
#pragma unroll
    for (int i = 0; i < 4; i++) {
        float4 a0 = *(const float4*)(src + (2 * i) * W);
        float4 a1 = *(const float4*)(src + (2 * i) * W + 4);
        float4 b0 = *(const float4*)(src + (2 * i + 1) * W);
        float4 b1 = *(const float4*)(src + (2 * i + 1) * W + 4);
        cA1[i][0] = 0.5f * (a0.x + a0.y + b0.x + b0.y);
        cA1[i][1] = 0.5f * (a0.z + a0.w + b0.z + b0.w);
        cA1[i][2] = 0.5f * (a1.x + a1.y + b1.x + b1.y);
        cA1[i][3] = 0.5f * (a1.z + a1.w + b1.z + b1.w);
    }
    float cA2[2][2];
#pragma unroll
    for (int i = 0; i < 2; i++)
#pragma unroll
        for (int j = 0; j < 2; j++) {
            float a = cA1[2 * i][2 * j],     b = cA1[2 * i][2 * j + 1];
            float c = cA1[2 * i + 1][2 * j], d = cA1[2 * i + 1][2 * j + 1];
            cA2[i][j] = 0.5f * (a + b + c + d);
        }
    float a = cA2[0][0], b = cA2[0][1], c = cA2[1][0], d = cA2[1][1];
    float cH3 = 0.5f * (a + b - c - d);
    float cV3 = 0.5f * (a - b + c - d);
    float cD3 = 0.5f * (a - b - c + d);

    float* dst = g_l3abs + (size_t)batch * L3N + gb * 3;
    dst[0] = fabsf(cH3);
    dst[1] = fabsf(cV3);
    dst[2] = fabsf(cD3);
}

// ---------------------------------------------------------------------------
// Pass 2: one block per batch. Exact median of 12288 nonneg floats via
// 8-bit radix select on the (monotone-for-nonneg) float bit patterns.
// jnp.median over an even count averages the two middle order statistics
// (k=6143, 6144). Values live in REGISTERS (48/thread) — only ~1 KB static
// smem, so no shared-memory launch-config hazard and no occupancy hit.
__global__ void __launch_bounds__(MED_THREADS) k_median(float* __restrict__ out) {
    __shared__ unsigned s_hist[256];
    __shared__ unsigned s_sel;
    __shared__ unsigned s_krem;

    const int batch = blockIdx.x;
    const int tid = threadIdx.x;
    const float* src = g_l3abs + (size_t)batch * L3N;

    // Coalesced one-time load of this thread's 48 candidates.
    unsigned v[VPT];
#pragma unroll
    for (int j = 0; j < VPT; j++)
        v[j] = __float_as_uint(src[tid + j * MED_THREADS]);

    unsigned med_bits[2];
#pragma unroll 1
    for (int sel = 0; sel < 2; sel++) {
        if (tid == 0) s_krem = (sel == 0) ? (unsigned)KMED_LO : (unsigned)KMED_HI;
        unsigned prefix = 0;
#pragma unroll 1
        for (int shift = 24; shift >= 0; shift -= 8) {
            if (tid < 256) s_hist[tid] = 0;   // MED_THREADS == 256
            __syncthreads();
#pragma unroll
            for (int j = 0; j < VPT; j++) {
                unsigned u = v[j];
                bool match = (shift == 24) || ((u >> (shift + 8)) == prefix);
                if (match) atomicAdd(&s_hist[(u >> shift) & 0xFFu], 1u);
            }
            __syncthreads();
            if (tid == 0) {
                unsigned cum = 0, kk = s_krem, bkt = 0;
                for (int bb = 0; bb < 256; bb++) {
                    unsigned h = s_hist[bb];
                    if (cum + h > kk) { bkt = (unsigned)bb; s_krem = kk - cum; break; }
                    cum += h;
                }
                s_sel = bkt;
            }
            __syncthreads();
            prefix = (prefix << 8) | s_sel;
        }
        med_bits[sel] = prefix;
    }

    if (tid == 0) {
        float median = 0.5f * (__uint_as_float(med_bits[0]) + __uint_as_float(med_bits[1]));
        float sigma = median * 1.4825796886582653f;   // 1/0.6745
        float thr = fminf(fmaxf(sigma * 2.5f, 0.05f), 0.2f);
        g_thr[batch] = thr;
        atomicAdd(&out[1], sigma * (1.0f / (float)BATCH));
    }
}

// ---------------------------------------------------------------------------
__device__ __forceinline__ float quad_detail(float a, float b, float c, float d,
                                             float t, float& cA) {
    float cH = 0.5f * (a + b - c - d);
    float cV = 0.5f * (a - b + c - d);
    float cD = 0.5f * (a - b - c + d);
    cA = 0.5f * (a + b + c + d);
    return fminf(fabsf(cH), t) + fminf(fabsf(cV), t) + fminf(fabsf(cD), t);
}

// Pass 3: recompute Haar per 8x8 block, accumulate weighted min(|c|,t) sums.
// |c - soft_threshold(c, t)| == min(|c|, t), so no target materialization.
__global__ void k_pass3(const float* __restrict__ in, float* __restrict__ out) {
    const int batch = blockIdx.y;
    const int gb = blockIdx.x * blockDim.x + threadIdx.x;
    const int br = gb >> 6;
    const int bc = gb & 63;
    const float* src = in + ((size_t)batch << 18) + (size_t)(br << 3) * W + (bc << 3);

    const float thr = g_thr[batch];
    const float t1 = 0.25f * thr;   // level-1 details (level_idx=3)
    const float t2 = 0.5f * thr;    // level-2 details (level_idx=2)
    const float t3 = thr;           // level-3 details (level_idx=1)

    float s1 = 0.0f, s2 = 0.0f;
    float cA1[4][4];
#pragma unroll
    for (int i = 0; i < 4; i++) {
        float4 a0 = *(const float4*)(src + (2 * i) * W);
        float4 a1 = *(const float4*)(src + (2 * i) * W + 4);
        float4 b0 = *(const float4*)(src + (2 * i + 1) * W);
        float4 b1 = *(const float4*)(src + (2 * i + 1) * W + 4);
        s1 += quad_detail(a0.x, a0.y, b0.x, b0.y, t1, cA1[i][0]);
        s1 += quad_detail(a0.z, a0.w, b0.z, b0.w, t1, cA1[i][1]);
        s1 += quad_detail(a1.x, a1.y, b1.x, b1.y, t1, cA1[i][2]);
        s1 += quad_detail(a1.z, a1.w, b1.z, b1.w, t1, cA1[i][3]);
    }
    float cA2[2][2];
#pragma unroll
    for (int i = 0; i < 2; i++)
#pragma unroll
        for (int j = 0; j < 2; j++)
            s2 += quad_detail(cA1[2 * i][2 * j], cA1[2 * i][2 * j + 1],
                              cA1[2 * i + 1][2 * j], cA1[2 * i + 1][2 * j + 1],
                              t2, cA2[i][j]);
    float cA3;
    float s3 = quad_detail(cA2[0][0], cA2[0][1], cA2[1][0], cA2[1][1], t3, cA3);

    // weights: level_idx l over detail level (4-l); mean over n_l elems; /3; /level_idx
    float s = s3 * (1.0f / (3.0f * 4096.0f))
            + s2 * (1.0f / (6.0f * 16384.0f))
            + s1 * (1.0f / (9.0f * 65536.0f));

    // block reduce
#pragma unroll
    for (int off = 16; off; off >>= 1) s += __shfl_xor_sync(0xFFFFFFFFu, s, off);
    __shared__ float warp_s[8];
    if ((threadIdx.x & 31) == 0) warp_s[threadIdx.x >> 5] = s;
    __syncthreads();
    if (threadIdx.x < 8) {
        float v = warp_s[threadIdx.x];
#pragma unroll
        for (int off = 4; off; off >>= 1) v += __shfl_xor_sync(0xFFu, v, off);
        if (threadIdx.x == 0) atomicAdd(&out[0], v * (1.0f / (float)BATCH));
    }
}

// ---------------------------------------------------------------------------
extern "C" void kernel_launch(void* const* d_in, const int* in_sizes, int n_in,
                              void* d_out, int out_size) {
    const float* pred = (const float*)d_in[0];
    float* out = (float*)d_out;

    // Pure kernel launches only; no dynamic smem anywhere.
    k_zero<<<1, 32>>>(out);
    k_pass1<<<dim3(16, BATCH), 256>>>(pred);
    k_median<<<BATCH, MED_THREADS>>>(out);
    k_pass3<<<dim3(16, BATCH), 256>>>(pred, out);
}

// round 9
// speedup vs baseline: 1.8881x; 1.8881x over previous
#include <cuda_runtime.h>

// Problem constants
static constexpr int BATCH = 128;
static constexpr int W = 512;
static constexpr int L3N = 3 * 4096;           // 12288 level-3 detail coeffs per batch
static constexpr int KMED_LO = (L3N / 2) - 1;  // 6143
static constexpr int KMED_HI = (L3N / 2);      // 6144
static constexpr int MED_THREADS = 256;
static constexpr int VPT = L3N / MED_THREADS;  // 48 values per thread

// Speculative threshold = upper clip bound (realized whenever sigma*2.5 >= 0.2).
#define SPEC_T 0.2f

// Scratch (no cudaMalloc allowed)
__device__ float g_l3abs[BATCH * L3N];
__device__ float g_thr[BATCH];
__device__ float g_sigma[BATCH];
__device__ float g_spec[BATCH];   // speculative per-batch loss sum (t = SPEC_T)
__device__ float g_fix[BATCH];    // recomputed per-batch loss sum (true t)

// ---------------------------------------------------------------------------
__global__ void k_zero() {
    if (threadIdx.x < BATCH) {
        g_spec[threadIdx.x] = 0.0f;
        g_fix[threadIdx.x] = 0.0f;
    }
}

// ---------------------------------------------------------------------------
__device__ __forceinline__ float quad_detail(float a, float b, float c, float d,
                                             float t, float& cA) {
    float cH = 0.5f * (a + b - c - d);
    float cV = 0.5f * (a - b + c - d);
    float cD = 0.5f * (a - b - c + d);
    cA = 0.5f * (a + b + c + d);
    return fminf(fabsf(cH), t) + fminf(fabsf(cV), t) + fminf(fabsf(cD), t);
}

// Per-thread 8x8 block: full 3-level Haar. Accumulates weighted min(|c|,t)
// loss with thresholds (t3, t2, t1) = (t, t/2, t/4) and optionally emits the
// level-3 abs details. Returns the weighted per-block loss contribution.
// |c - soft_threshold(c,t)| == min(|c|, t), so no target materialization.
__device__ __forceinline__ float block_loss(const float* __restrict__ src,
                                            float t3, float* l3dst) {
    const float t2 = 0.5f * t3;
    const float t1 = 0.25f * t3;
    float s1 = 0.0f, s2 = 0.0f;
    float cA1[4][4];
#pragma unroll
    for (int i = 0; i < 4; i++) {
        float4 a0 = *(const float4*)(src + (2 * i) * W);
        float4 a1 = *(const float4*)(src + (2 * i) * W + 4);
        float4 b0 = *(const float4*)(src + (2 * i + 1) * W);
        float4 b1 = *(const float4*)(src + (2 * i + 1) * W + 4);
        s1 += quad_detail(a0.x, a0.y, b0.x, b0.y, t1, cA1[i][0]);
        s1 += quad_detail(a0.z, a0.w, b0.z, b0.w, t1, cA1[i][1]);
        s1 += quad_detail(a1.x, a1.y, b1.x, b1.y, t1, cA1[i][2]);
        s1 += quad_detail(a1.z, a1.w, b1.z, b1.w, t1, cA1[i][3]);
    }
    float cA2[2][2];
#pragma unroll
    for (int i = 0; i < 2; i++)
#pragma unroll
        for (int j = 0; j < 2; j++)
            s2 += quad_detail(cA1[2 * i][2 * j], cA1[2 * i][2 * j + 1],
                              cA1[2 * i + 1][2 * j], cA1[2 * i + 1][2 * j + 1],
                              t2, cA2[i][j]);

    float a = cA2[0][0], b = cA2[0][1], c = cA2[1][0], d = cA2[1][1];
    float cH3 = 0.5f * (a + b - c - d);
    float cV3 = 0.5f * (a - b + c - d);
    float cD3 = 0.5f * (a - b - c + d);
    float s3 = fminf(fabsf(cH3), t3) + fminf(fabsf(cV3), t3) + fminf(fabsf(cD3), t3);
    if (l3dst) {
        l3dst[0] = fabsf(cH3);
        l3dst[1] = fabsf(cV3);
        l3dst[2] = fabsf(cD3);
    }
    // weights: level_idx l over detail level (4-l); mean over n_l; /3; /level_idx
    return s3 * (1.0f / (3.0f * 4096.0f))
         + s2 * (1.0f / (6.0f * 16384.0f))
         + s1 * (1.0f / (9.0f * 65536.0f));
}

__device__ __forceinline__ void block_reduce_atomic(float s, float* dst) {
#pragma unroll
    for (int off = 16; off; off >>= 1) s += __shfl_xor_sync(0xFFFFFFFFu, s, off);
    __shared__ float warp_s[8];
    if ((threadIdx.x & 31) == 0) warp_s[threadIdx.x >> 5] = s;
    __syncthreads();
    if (threadIdx.x < 8) {
        float v = warp_s[threadIdx.x];
#pragma unroll
        for (int off = 4; off; off >>= 1) v += __shfl_xor_sync(0xFFu, v, off);
        if (threadIdx.x == 0) atomicAdd(dst, v);
    }
}

// ---------------------------------------------------------------------------
// Pass 1: single read of pred. Emits level-3 |details| (for the median) AND
// the speculative loss at t = SPEC_T (the clip upper bound, which the data
// realizes whenever sigma*2.5 >= 0.2).
__global__ void k_pass1(const float* __restrict__ in) {
    const int batch = blockIdx.y;
    const int gb = blockIdx.x * blockDim.x + threadIdx.x;   // 0..4095
    const float* src = in + ((size_t)batch << 18)
                          + (size_t)((gb >> 6) << 3) * W + ((gb & 63) << 3);
    float s = block_loss(src, SPEC_T, g_l3abs + (size_t)batch * L3N + gb * 3);
    block_reduce_atomic(s, &g_spec[batch]);
}

// ---------------------------------------------------------------------------
// Median: one block per batch. Exact k=6143 order statistic via 4-pass 8-bit
// radix select on nonneg float bit patterns (values in registers, parallel
// 256-bin block scan). k=6144 derived from count(<=) + min(> medLO).
__global__ void __launch_bounds__(MED_THREADS) k_median() {
    __shared__ unsigned s_hist[256];
    __shared__ unsigned s_scan[256];
    __shared__ unsigned s_sel;
    __shared__ unsigned s_krem;
    __shared__ unsigned s_red[8];

    const int batch = blockIdx.x;
    const int tid = threadIdx.x;
    const float* src = g_l3abs + (size_t)batch * L3N;

    unsigned v[VPT];
#pragma unroll
    for (int j = 0; j < VPT; j++)
        v[j] = __float_as_uint(src[tid + j * MED_THREADS]);

    if (tid == 0) s_krem = (unsigned)KMED_LO;
    unsigned prefix = 0;
#pragma unroll 1
    for (int shift = 24; shift >= 0; shift -= 8) {
        s_hist[tid] = 0;
        __syncthreads();
#pragma unroll
        for (int j = 0; j < VPT; j++) {
            unsigned u = v[j];
            bool match = (shift == 24) || ((u >> (shift + 8)) == prefix);
            if (match) atomicAdd(&s_hist[(u >> shift) & 0xFFu], 1u);
        }
        __syncthreads();
        // Hillis-Steele inclusive scan over 256 bins
        unsigned h = s_hist[tid];
        s_scan[tid] = h;
        __syncthreads();
#pragma unroll
        for (int off = 1; off < 256; off <<= 1) {
            unsigned t = (tid >= off) ? s_scan[tid - off] : 0u;
            __syncthreads();
            s_scan[tid] += t;
            __syncthreads();
        }
        unsigned excl = s_scan[tid] - h;
        unsigned kk = s_krem;
        if (kk >= excl && kk < excl + h) {   // unique winner (h > 0)
            s_sel = (unsigned)tid;
            s_krem = kk - excl;
        }
        __syncthreads();
        prefix = (prefix << 8) | s_sel;
        __syncthreads();
    }
    const unsigned medLO = prefix;

    // count(v <= medLO) and min over v > medLO, reduced across the block
    unsigned cnt = 0, mn = 0x7F800000u;
#pragma unroll
    for (int j = 0; j < VPT; j++) {
        if (v[j] <= medLO) cnt++;
        else mn = min(mn, v[j]);
    }
#pragma unroll
    for (int off = 16; off; off >>= 1) {
        cnt += __shfl_xor_sync(0xFFFFFFFFu, cnt, off);
        mn = min(mn, __shfl_xor_sync(0xFFFFFFFFu, mn, off));
    }
    if ((tid & 31) == 0) { s_hist[tid >> 5] = cnt; s_red[tid >> 5] = mn; }
    __syncthreads();
    if (tid == 0) {
        unsigned ctot = 0, mtot = 0x7F800000u;
#pragma unroll
        for (int w = 0; w < 8; w++) { ctot += s_hist[w]; mtot = min(mtot, s_red[w]); }
        unsigned medHI = (ctot > (unsigned)KMED_HI) ? medLO : mtot;
        float median = 0.5f * (__uint_as_float(medLO) + __uint_as_float(medHI));
        float sigma = median * 1.4825796886582653f;   // 1/0.6745
        g_sigma[batch] = sigma;
        g_thr[batch] = fminf(fmaxf(sigma * 2.5f, 0.05f), SPEC_T);
    }
}

// ---------------------------------------------------------------------------
// Fixup: only batches whose true threshold differs from SPEC_T re-read pred.
// Common case: every block loads one L2-resident float and returns.
__global__ void k_fix(const float* __restrict__ in) {
    const int batch = blockIdx.y;
    const float thr = g_thr[batch];
    if (thr == SPEC_T) return;   // uniform across block
    const int gb = blockIdx.x * blockDim.x + threadIdx.x;
    const float* src = in + ((size_t)batch << 18)
                          + (size_t)((gb >> 6) << 3) * W + ((gb & 63) << 3);
    float s = block_loss(src, thr, nullptr);
    block_reduce_atomic(s, &g_fix[batch]);
}

// ---------------------------------------------------------------------------
// Final: pick spec/fix per batch, average, write both outputs.
__global__ void k_final(float* __restrict__ out) {
    const int tid = threadIdx.x;   // 128 threads
    float l = (g_thr[tid] == SPEC_T) ? g_spec[tid] : g_fix[tid];
    float sg = g_sigma[tid];
#pragma unroll
    for (int off = 16; off; off >>= 1) {
        l += __shfl_xor_sync(0xFFFFFFFFu, l, off);
        sg += __shfl_xor_sync(0xFFFFFFFFu, sg, off);
    }
    __shared__ float sl[4], ss[4];
    if ((tid & 31) == 0) { sl[tid >> 5] = l; ss[tid >> 5] = sg; }
    __syncthreads();
    if (tid == 0) {
        float L = sl[0] + sl[1] + sl[2] + sl[3];
        float S = ss[0] + ss[1] + ss[2] + ss[3];
        out[0] = L * (1.0f / (float)BATCH);
        out[1] = S * (1.0f / (float)BATCH);
    }
}

// ---------------------------------------------------------------------------
extern "C" void kernel_launch(void* const* d_in, const int* in_sizes, int n_in,
                              void* d_out, int out_size) {
    const float* pred = (const float*)d_in[0];
    float* out = (float*)d_out;

    k_zero<<<1, 256>>>();
    k_pass1<<<dim3(16, BATCH), 256>>>(pred);
    k_median<<<BATCH, MED_THREADS>>>();
    k_fix<<<dim3(16, BATCH), 256>>>(pred);
    k_final<<<1, 128>>>(out);
}